// round 3
// baseline (speedup 1.0000x reference)
#include <cuda_runtime.h>
#include <cuda_bf16.h>

typedef unsigned long long ull;

#define BB 8
#define NP 8192
#define NQ 1024
#define KNN 32
#define F1 64

// scratch: neighbor indices (radius-clamped), B*N2*K
__device__ int g_nbr[BB * NQ * KNN];

// ---------------------------------------------------------------------------
// Kernel 1: farthest point sampling. 1 block per batch, 1024 threads.
// Writes selected_xyz directly into out[0 .. B*N2*3).
// ---------------------------------------------------------------------------
__global__ void __launch_bounds__(1024) fps_kernel(const float* __restrict__ xyz,
                                                   float* __restrict__ out)
{
    extern __shared__ float s[];            // 3 * 8192 floats = 96KB
    float* sx = s;
    float* sy = s + NP;
    float* sz = s + 2 * NP;
    __shared__ float swv[32];
    __shared__ int   swi[32];
    __shared__ float cur[3];

    const int b = blockIdx.x;
    const int t = threadIdx.x;
    const float* p = xyz + (size_t)b * NP * 3;

    float px[8], py[8], pz[8], md[8];
#pragma unroll
    for (int i = 0; i < 8; i++) {
        int pi = t + i * 1024;
        float x = p[pi * 3 + 0];
        float y = p[pi * 3 + 1];
        float z = p[pi * 3 + 2];
        px[i] = x; py[i] = y; pz[i] = z;
        sx[pi] = x; sy[pi] = y; sz[pi] = z;
        md[i] = 3.402823466e38f;
    }
    __syncthreads();

    float* oxyz = out + (size_t)b * NQ * 3;
    if (t == 0) {
        cur[0] = sx[0]; cur[1] = sy[0]; cur[2] = sz[0];
        oxyz[0] = sx[0]; oxyz[1] = sy[0]; oxyz[2] = sz[0];
    }
    __syncthreads();

    for (int si = 1; si < NQ; si++) {
        float cx = cur[0], cy = cur[1], cz = cur[2];
        float bv = -1.0f;
        int   bi = 0;
#pragma unroll
        for (int i = 0; i < 8; i++) {
            float dx = px[i] - cx;
            float dy = py[i] - cy;
            float dz = pz[i] - cz;
            float d = dx * dx + dy * dy + dz * dz;
            float m = fminf(md[i], d);
            md[i] = m;
            if (m > bv) { bv = m; bi = t + i * 1024; }
        }
        // warp argmax (tie -> lower index)
#pragma unroll
        for (int o = 16; o > 0; o >>= 1) {
            float ov = __shfl_down_sync(0xffffffffu, bv, o);
            int   oi = __shfl_down_sync(0xffffffffu, bi, o);
            if (ov > bv || (ov == bv && oi < bi)) { bv = ov; bi = oi; }
        }
        if ((t & 31) == 0) { swv[t >> 5] = bv; swi[t >> 5] = bi; }
        __syncthreads();
        if (t < 32) {
            bv = swv[t]; bi = swi[t];
#pragma unroll
            for (int o = 16; o > 0; o >>= 1) {
                float ov = __shfl_down_sync(0xffffffffu, bv, o);
                int   oi = __shfl_down_sync(0xffffffffu, bi, o);
                if (ov > bv || (ov == bv && oi < bi)) { bv = ov; bi = oi; }
            }
            if (t == 0) {
                float wx = sx[bi], wy = sy[bi], wz = sz[bi];
                cur[0] = wx; cur[1] = wy; cur[2] = wz;
                oxyz[si * 3 + 0] = wx;
                oxyz[si * 3 + 1] = wy;
                oxyz[si * 3 + 2] = wz;
            }
        }
        __syncthreads();
    }
}

// ---------------------------------------------------------------------------
// Kernel 2: exact 32-NN (matching lax.top_k stable semantics) + radius clamp.
// 256 blocks x 32 threads: 1 warp/block, 1 thread = 1 query.
// Threshold kept in the ENCODED unsigned domain (monotonic order transform):
// decoding the ~0 sentinel to float yields NaN and poisons the compare.
// ---------------------------------------------------------------------------
__global__ void __launch_bounds__(32) knn_kernel(const float* __restrict__ xyz,
                                                 const float* __restrict__ out)
{
    __shared__ float4 sp[1024];             // 16KB tile

    const int b  = blockIdx.x >> 5;
    const int q  = ((blockIdx.x & 31) << 5) + threadIdx.x;
    const int gq = b * NQ + q;

    const float qx = out[gq * 3 + 0];
    const float qy = out[gq * 3 + 1];
    const float qz = out[gq * 3 + 2];
    const float q2 = fmaf(qx, qx, fmaf(qy, qy, qz * qz));

    ull arr[KNN];
#pragma unroll
    for (int k = 0; k < KNN; k++) arr[k] = ~0ull;
    unsigned hi31 = 0xffffffffu;            // encoded d2 of current 32nd-best

    const float* p = xyz + (size_t)b * NP * 3;

    for (int tile = 0; tile < 8; tile++) {
        const int base = tile << 10;
        for (int j = threadIdx.x; j < 1024; j += 32) {
            float x = p[(base + j) * 3 + 0];
            float y = p[(base + j) * 3 + 1];
            float z = p[(base + j) * 3 + 2];
            sp[j] = make_float4(x, y, z, fmaf(x, x, fmaf(y, y, z * z)));
        }
        __syncthreads();
#pragma unroll 2
        for (int j = 0; j < 1024; j++) {
            float4 P = sp[j];
            float qp = fmaf(qx, P.x, fmaf(qy, P.y, qz * P.z));
            float d2 = fmaf(-2.0f, qp, q2 + P.w);
            unsigned du = __float_as_uint(d2);
            du ^= (unsigned)((int)du >> 31) | 0x80000000u;   // ordered transform
            // strict <: equal-d2 later-index loses (matches stable top_k); the
            // ~0 sentinel (0xffffffff) always admits finite candidates.
            if (du < hi31) {
                ull key = ((ull)du << 32) | (unsigned)(base + j);
                bool placed = false;
#pragma unroll
                for (int m = KNN - 1; m > 0; --m) {
                    if (!placed) {
                        if (key < arr[m - 1]) { arr[m] = arr[m - 1]; }
                        else { arr[m] = key; placed = true; }
                    }
                }
                if (!placed) arr[0] = key;
                hi31 = (unsigned)(arr[KNN - 1] >> 32);
            }
        }
        __syncthreads();
    }

    const int near = (int)(arr[0] & 0xffffffffu);
    const float r2 = 0.2f * 0.2f;
    const unsigned r2u = __float_as_uint(r2) ^ 0x80000000u;  // encoded +r2
#pragma unroll
    for (int k = 0; k < KNN; k++) {
        unsigned du = (unsigned)(arr[k] >> 32);
        int idx = (int)(arr[k] & 0xffffffffu);
        g_nbr[gq * KNN + k] = (du > r2u) ? near : idx;
    }
}

// ---------------------------------------------------------------------------
// Kernel 3: gather + MLP(67->64->64->128, leaky 0.2) + max over K.
// warp = query, lane = neighbor. Packed f32x2 FMA for 2x fp32 throughput.
// ---------------------------------------------------------------------------
__device__ __forceinline__ void fma2(ull& d, ull a, ull b)
{
    asm("fma.rn.f32x2 %0, %1, %2, %0;" : "+l"(d) : "l"(a), "l"(b));
}
__device__ __forceinline__ ull bc2(float x)
{
    ull r;
    asm("mov.b64 %0, {%1, %1};" : "=l"(r) : "f"(x));
    return r;
}
__device__ __forceinline__ float2 unpk(ull r)
{
    float2 v;
    asm("mov.b64 {%0, %1}, %2;" : "=f"(v.x), "=f"(v.y) : "l"(r));
    return v;
}
__device__ __forceinline__ float lrelu(float x) { return fmaxf(x, 0.2f * x); }

template <int NU>
__device__ __forceinline__ void accum_row(ull* acc, const float* wrow, float xc)
{
    ull xv = bc2(xc);
    const ulonglong2* w = (const ulonglong2*)wrow;
#pragma unroll
    for (int jj = 0; jj < NU / 2; jj++) {
        ulonglong2 ww = w[jj];
        fma2(acc[2 * jj + 0], xv, ww.x);
        fma2(acc[2 * jj + 1], xv, ww.y);
    }
}

#define OW0 0
#define OB0 4288
#define OW1 4352
#define OB1 8448
#define OW2 8512
#define OB2 16704
#define OPOOL 16832
#define SMEM_MLP_FLOATS (OPOOL + 4 * 128)
#define SMEM_MLP_BYTES (SMEM_MLP_FLOATS * 4)

__global__ void __launch_bounds__(128, 3) mlp_kernel(
    const float* __restrict__ xyz, const float* __restrict__ feat,
    const float* __restrict__ W0, const float* __restrict__ b0,
    const float* __restrict__ W1, const float* __restrict__ b1,
    const float* __restrict__ W2, const float* __restrict__ b2,
    float* __restrict__ out)
{
    extern __shared__ float sm[];
    // cooperative weight staging
    for (int i = threadIdx.x; i < OPOOL; i += 128) {
        float v;
        if (i < OB0)        v = W0[i];
        else if (i < OW1)   v = b0[i - OB0];
        else if (i < OB1)   v = W1[i - OW1];
        else if (i < OW2)   v = b1[i - OB1];
        else if (i < OB2)   v = W2[i - OW2];
        else                v = b2[i - OB2];
        sm[i] = v;
    }
    __syncthreads();

    const int warp = threadIdx.x >> 5;
    const int lane = threadIdx.x & 31;
    const int q = blockIdx.x * 4 + warp;
    const int b = q >> 10;

    const int nidx = g_nbr[q * KNN + lane];
    const float cx = out[q * 3 + 0];
    const float cy = out[q * 3 + 1];
    const float cz = out[q * 3 + 2];
    const float* pp = xyz + ((size_t)b * NP + nidx) * 3;
    const float x0 = pp[0] - cx;
    const float x1 = pp[1] - cy;
    const float x2 = pp[2] - cz;
    const float4* pf = (const float4*)(feat + ((size_t)b * NP + nidx) * F1);

    // ---- layer 1: 67 -> 64 ----
    ull a1[32];
    {
        const ull* bb = (const ull*)(sm + OB0);
#pragma unroll
        for (int j = 0; j < 32; j++) a1[j] = bb[j];
    }
    accum_row<32>(a1, sm + OW0 + 0 * 64, x0);
    accum_row<32>(a1, sm + OW0 + 1 * 64, x1);
    accum_row<32>(a1, sm + OW0 + 2 * 64, x2);
#pragma unroll
    for (int g = 0; g < 16; g++) {
        float4 f = pf[g];
        accum_row<32>(a1, sm + OW0 + (3 + 4 * g + 0) * 64, f.x);
        accum_row<32>(a1, sm + OW0 + (3 + 4 * g + 1) * 64, f.y);
        accum_row<32>(a1, sm + OW0 + (3 + 4 * g + 2) * 64, f.z);
        accum_row<32>(a1, sm + OW0 + (3 + 4 * g + 3) * 64, f.w);
    }
    float h1[64];
#pragma unroll
    for (int j = 0; j < 32; j++) {
        float2 v = unpk(a1[j]);
        h1[2 * j + 0] = lrelu(v.x);
        h1[2 * j + 1] = lrelu(v.y);
    }

    // ---- layer 2: 64 -> 64 ----
    ull a2[32];
    {
        const ull* bb = (const ull*)(sm + OB1);
#pragma unroll
        for (int j = 0; j < 32; j++) a2[j] = bb[j];
    }
#pragma unroll
    for (int c = 0; c < 64; c++) accum_row<32>(a2, sm + OW1 + c * 64, h1[c]);
    float h2[64];
#pragma unroll
    for (int j = 0; j < 32; j++) {
        float2 v = unpk(a2[j]);
        h2[2 * j + 0] = lrelu(v.x);
        h2[2 * j + 1] = lrelu(v.y);
    }

    // ---- layer 3: 64 -> 128, in 4 chunks of 32, fused warp max-pool ----
    float* pool = sm + OPOOL + warp * 128;
#pragma unroll
    for (int ch = 0; ch < 4; ch++) {
        ull a3[16];
        {
            const ull* bb = (const ull*)(sm + OB2);
#pragma unroll
            for (int j = 0; j < 16; j++) a3[j] = bb[ch * 16 + j];
        }
#pragma unroll
        for (int c = 0; c < 64; c++)
            accum_row<16>(a3, sm + OW2 + c * 128 + ch * 32, h2[c]);
#pragma unroll
        for (int j = 0; j < 16; j++) {
            float2 v = unpk(a3[j]);
            float v0 = lrelu(v.x);
            float v1 = lrelu(v.y);
#pragma unroll
            for (int o = 16; o > 0; o >>= 1) {
                v0 = fmaxf(v0, __shfl_down_sync(0xffffffffu, v0, o));
                v1 = fmaxf(v1, __shfl_down_sync(0xffffffffu, v1, o));
            }
            if (lane == 0) {
                pool[ch * 32 + 2 * j + 0] = v0;
                pool[ch * 32 + 2 * j + 1] = v1;
            }
        }
    }
    __syncwarp();
    float4* dst = (float4*)(out + BB * NQ * 3 + (size_t)q * 128);
    dst[lane] = ((const float4*)pool)[lane];
}

// ---------------------------------------------------------------------------
extern "C" void kernel_launch(void* const* d_in, const int* in_sizes, int n_in,
                              void* d_out, int out_size)
{
    const float* xyz  = (const float*)d_in[0];
    const float* feat = (const float*)d_in[1];
    const float* W0   = (const float*)d_in[2];
    const float* b0   = (const float*)d_in[3];
    const float* W1   = (const float*)d_in[4];
    const float* b1   = (const float*)d_in[5];
    const float* W2   = (const float*)d_in[6];
    const float* b2   = (const float*)d_in[7];
    float* out = (float*)d_out;

    cudaFuncSetAttribute(fps_kernel, cudaFuncAttributeMaxDynamicSharedMemorySize,
                         3 * NP * 4);
    cudaFuncSetAttribute(mlp_kernel, cudaFuncAttributeMaxDynamicSharedMemorySize,
                         SMEM_MLP_BYTES);

    fps_kernel<<<BB, 1024, 3 * NP * 4>>>(xyz, out);
    knn_kernel<<<BB * 32, 32>>>(xyz, out);
    mlp_kernel<<<(BB * NQ) / 4, 128, SMEM_MLP_BYTES>>>(xyz, feat, W0, b0, W1, b1,
                                                       W2, b2, out);
}

// round 4
// speedup vs baseline: 6.8423x; 6.8423x over previous
#include <cuda_runtime.h>
#include <cuda_bf16.h>

typedef unsigned long long ull;

#define BB 8
#define NP 8192
#define NQ 1024
#define KNN 32
#define F1 64

// scratch: neighbor indices (radius-resolved), B*N2*K
__device__ int g_nbr[BB * NQ * KNN];

// ---------------- packed f32x2 helpers ----------------
union F2 { ull u; float2 f; };

__device__ __forceinline__ ull add2(ull a, ull b)
{
    ull r; asm("add.rn.f32x2 %0, %1, %2;" : "=l"(r) : "l"(a), "l"(b)); return r;
}
__device__ __forceinline__ ull mul2(ull a, ull b)
{
    ull r; asm("mul.rn.f32x2 %0, %1, %2;" : "=l"(r) : "l"(a), "l"(b)); return r;
}
__device__ __forceinline__ void fma2(ull& d, ull a, ull b)
{
    asm("fma.rn.f32x2 %0, %1, %2, %0;" : "+l"(d) : "l"(a), "l"(b));
}
__device__ __forceinline__ ull bc2(float x)
{
    ull r; asm("mov.b64 %0, {%1, %1};" : "=l"(r) : "f"(x)); return r;
}
__device__ __forceinline__ float2 unpk(ull r)
{
    float2 v; asm("mov.b64 {%0, %1}, %2;" : "=f"(v.x), "=f"(v.y) : "l"(r)); return v;
}
__device__ __forceinline__ float lrelu(float x) { return fmaxf(x, 0.2f * x); }

// ---------------------------------------------------------------------------
// Kernel 1: FPS. 1 block/batch, 1024 threads, 8 pts/thread in registers.
// Value-only block argmax; winner thread supplies coords from registers.
// ---------------------------------------------------------------------------
__global__ void __launch_bounds__(1024) fps_kernel(const float* __restrict__ xyz,
                                                   float* __restrict__ out)
{
    __shared__ float swv[32];
    __shared__ float cur[3];
    __shared__ int   swin;

    const int b = blockIdx.x;
    const int t = threadIdx.x;
    const float* p = xyz + (size_t)b * NP * 3;

    ull px[4], py[4], pz[4];
    float md[8];
#pragma unroll
    for (int i = 0; i < 4; i++) {
        int i0 = t + (2 * i) * 1024;
        int i1 = t + (2 * i + 1) * 1024;
        F2 X, Y, Z;
        X.f.x = p[i0 * 3 + 0]; Y.f.x = p[i0 * 3 + 1]; Z.f.x = p[i0 * 3 + 2];
        X.f.y = p[i1 * 3 + 0]; Y.f.y = p[i1 * 3 + 1]; Z.f.y = p[i1 * 3 + 2];
        px[i] = X.u; py[i] = Y.u; pz[i] = Z.u;
        md[2 * i] = 3.402823466e38f;
        md[2 * i + 1] = 3.402823466e38f;
    }
    if (t == 0) {
        cur[0] = p[0]; cur[1] = p[1]; cur[2] = p[2];
        float* o = out + (size_t)b * NQ * 3;
        o[0] = p[0]; o[1] = p[1]; o[2] = p[2];
        swin = 0x7fffffff;
    }
    __syncthreads();

    for (int si = 1; si < NQ; si++) {
        const float cx = cur[0], cy = cur[1], cz = cur[2];
        const ull ncx = bc2(-cx), ncy = bc2(-cy), ncz = bc2(-cz);
        float tv = -1.0f;
#pragma unroll
        for (int i = 0; i < 4; i++) {
            ull dx = add2(px[i], ncx);
            ull dy = add2(py[i], ncy);
            ull dz = add2(pz[i], ncz);
            ull d = mul2(dx, dx);
            fma2(d, dy, dy);
            fma2(d, dz, dz);
            float2 D = unpk(d);
            md[2 * i]     = fminf(md[2 * i], D.x);
            md[2 * i + 1] = fminf(md[2 * i + 1], D.y);
            tv = fmaxf(tv, md[2 * i]);
            tv = fmaxf(tv, md[2 * i + 1]);
        }
        // warp max (value only)
        float wv = tv;
#pragma unroll
        for (int o = 16; o > 0; o >>= 1)
            wv = fmaxf(wv, __shfl_xor_sync(0xffffffffu, wv, o));
        if ((t & 31) == 0) swv[t >> 5] = wv;
        __syncthreads();                                   // (1)
        if (t < 32) {
            float v = swv[t];
#pragma unroll
            for (int o = 16; o > 0; o >>= 1)
                v = fmaxf(v, __shfl_xor_sync(0xffffffffu, v, o));
            if (t == 0) { swv[0] = v; swin = 0x7fffffff; }
        }
        __syncthreads();                                   // (2)
        const float bv = swv[0];
        int mypi = -1;
        if (tv == bv) {
            // smallest matching slot for this thread (descending scan)
#pragma unroll
            for (int i = 7; i >= 0; i--)
                if (md[i] == bv) mypi = t + i * 1024;
            atomicMin(&swin, mypi);
        }
        __syncthreads();                                   // (3)
        if (mypi >= 0 && mypi == swin) {
            int i = (mypi - t) >> 10;
            float wx = 0.f, wy = 0.f, wz = 0.f;
#pragma unroll
            for (int j = 0; j < 8; j++)
                if (j == i) {
                    float2 X = unpk(px[j >> 1]);
                    float2 Y = unpk(py[j >> 1]);
                    float2 Z = unpk(pz[j >> 1]);
                    wx = (j & 1) ? X.y : X.x;
                    wy = (j & 1) ? Y.y : Y.x;
                    wz = (j & 1) ? Z.y : Z.x;
                }
            cur[0] = wx; cur[1] = wy; cur[2] = wz;
            float* o = out + (size_t)b * NQ * 3 + si * 3;
            o[0] = wx; o[1] = wy; o[2] = wz;
        }
        __syncthreads();                                   // (4)
    }
}

// ---------------------------------------------------------------------------
// Kernel 2: warp-per-query 32-NN with radius pre-prune.
// Needed set (exact, given max-pool + ball-query replacement) =
// top-min(32, T) of points with d2 <= r^2, padded with the nearest (self).
// Keys (encoded d2, idx) reproduce lax.top_k stable-tie semantics exactly.
// ---------------------------------------------------------------------------
__global__ void __launch_bounds__(256) knn_kernel(const float* __restrict__ xyz,
                                                  const float* __restrict__ outxyz)
{
    __shared__ float4 sp[1024];                 // 16KB tile

    const int warp = threadIdx.x >> 5;
    const int lane = threadIdx.x & 31;
    const int gq = blockIdx.x * 8 + warp;       // global query id
    const int b = blockIdx.x >> 7;              // 128 blocks per batch

    const float qx = outxyz[gq * 3 + 0];
    const float qy = outxyz[gq * 3 + 1];
    const float qz = outxyz[gq * 3 + 2];
    const float q2 = fmaf(qx, qx, fmaf(qy, qy, qz * qz));

    ull arr[KNN];                               // local mem, sorted ascending
    int cnt = 0;
    ull klim = ~0ull;
    const unsigned r2u = __float_as_uint(0.04f) ^ 0x80000000u;

    const float* p = xyz + (size_t)b * NP * 3;

    for (int tile = 0; tile < 8; tile++) {
        const int base = tile << 10;
        for (int j = threadIdx.x; j < 1024; j += 256) {
            float x = p[(base + j) * 3 + 0];
            float y = p[(base + j) * 3 + 1];
            float z = p[(base + j) * 3 + 2];
            sp[j] = make_float4(x, y, z, fmaf(x, x, fmaf(y, y, z * z)));
        }
        __syncthreads();
#pragma unroll 4
        for (int jj = 0; jj < 32; jj++) {
            const int j = (jj << 5) + lane;
            float4 P = sp[j];
            float qp = fmaf(qx, P.x, fmaf(qy, P.y, qz * P.z));
            float d2 = fmaf(-2.0f, qp, q2 + P.w);
            unsigned du = __float_as_uint(d2);
            du ^= (unsigned)((int)du >> 31) | 0x80000000u;   // ordered transform
            if (du <= r2u) {                                 // within radius
                ull key = ((ull)du << 32) | (unsigned)(base + j);
                if (key < klim) {                            // beats current 32nd
                    int m;
                    if (cnt < KNN) { m = cnt; cnt++; }
                    else m = KNN - 1;
                    while (m > 0 && arr[m - 1] > key) { arr[m] = arr[m - 1]; m--; }
                    arr[m] = key;
                    if (cnt == KNN) klim = arr[KNN - 1];
                }
            }
        }
        __syncthreads();
    }

    // exact warp merge: 32 rounds of extract-min over per-lane sorted lists
    ull h = (cnt > 0) ? arr[0] : ~0ull;
    int ptr = 1;
    int nearidx = 0;
    int* dst = g_nbr + (size_t)gq * KNN;
    for (int k = 0; k < KNN; k++) {
        ull m = h;
#pragma unroll
        for (int o = 16; o > 0; o >>= 1) {
            ull x = __shfl_xor_sync(0xffffffffu, m, o);
            if (x < m) m = x;
        }
        if (k == 0) nearidx = (int)(m & 0xffffffffu);    // self (d2~0) always within
        int wi = (m == ~0ull) ? nearidx : (int)(m & 0xffffffffu);
        if (lane == k) dst[k] = wi;
        if (h == m && m != ~0ull)
            h = (ptr < cnt) ? arr[ptr++] : ~0ull;
    }
}

// ---------------------------------------------------------------------------
// Kernel 3: gather + MLP(67->64->64->128, leaky 0.2) + max over K (unchanged).
// ---------------------------------------------------------------------------
template <int NU>
__device__ __forceinline__ void accum_row(ull* acc, const float* wrow, float xc)
{
    ull xv = bc2(xc);
    const ulonglong2* w = (const ulonglong2*)wrow;
#pragma unroll
    for (int jj = 0; jj < NU / 2; jj++) {
        ulonglong2 ww = w[jj];
        fma2(acc[2 * jj + 0], xv, ww.x);
        fma2(acc[2 * jj + 1], xv, ww.y);
    }
}

#define OW0 0
#define OB0 4288
#define OW1 4352
#define OB1 8448
#define OW2 8512
#define OB2 16704
#define OPOOL 16832
#define SMEM_MLP_FLOATS (OPOOL + 4 * 128)
#define SMEM_MLP_BYTES (SMEM_MLP_FLOATS * 4)

__global__ void __launch_bounds__(128, 3) mlp_kernel(
    const float* __restrict__ xyz, const float* __restrict__ feat,
    const float* __restrict__ W0, const float* __restrict__ b0,
    const float* __restrict__ W1, const float* __restrict__ b1,
    const float* __restrict__ W2, const float* __restrict__ b2,
    float* __restrict__ out)
{
    extern __shared__ float sm[];
    for (int i = threadIdx.x; i < OPOOL; i += 128) {
        float v;
        if (i < OB0)        v = W0[i];
        else if (i < OW1)   v = b0[i - OB0];
        else if (i < OB1)   v = W1[i - OW1];
        else if (i < OW2)   v = b1[i - OB1];
        else if (i < OB2)   v = W2[i - OW2];
        else                v = b2[i - OB2];
        sm[i] = v;
    }
    __syncthreads();

    const int warp = threadIdx.x >> 5;
    const int lane = threadIdx.x & 31;
    const int q = blockIdx.x * 4 + warp;
    const int b = q >> 10;

    const int nidx = g_nbr[q * KNN + lane];
    const float cx = out[q * 3 + 0];
    const float cy = out[q * 3 + 1];
    const float cz = out[q * 3 + 2];
    const float* pp = xyz + ((size_t)b * NP + nidx) * 3;
    const float x0 = pp[0] - cx;
    const float x1 = pp[1] - cy;
    const float x2 = pp[2] - cz;
    const float4* pf = (const float4*)(feat + ((size_t)b * NP + nidx) * F1);

    // ---- layer 1: 67 -> 64 ----
    ull a1[32];
    {
        const ull* bb = (const ull*)(sm + OB0);
#pragma unroll
        for (int j = 0; j < 32; j++) a1[j] = bb[j];
    }
    accum_row<32>(a1, sm + OW0 + 0 * 64, x0);
    accum_row<32>(a1, sm + OW0 + 1 * 64, x1);
    accum_row<32>(a1, sm + OW0 + 2 * 64, x2);
#pragma unroll
    for (int g = 0; g < 16; g++) {
        float4 f = pf[g];
        accum_row<32>(a1, sm + OW0 + (3 + 4 * g + 0) * 64, f.x);
        accum_row<32>(a1, sm + OW0 + (3 + 4 * g + 1) * 64, f.y);
        accum_row<32>(a1, sm + OW0 + (3 + 4 * g + 2) * 64, f.z);
        accum_row<32>(a1, sm + OW0 + (3 + 4 * g + 3) * 64, f.w);
    }
    float h1[64];
#pragma unroll
    for (int j = 0; j < 32; j++) {
        float2 v = unpk(a1[j]);
        h1[2 * j + 0] = lrelu(v.x);
        h1[2 * j + 1] = lrelu(v.y);
    }

    // ---- layer 2: 64 -> 64 ----
    ull a2[32];
    {
        const ull* bb = (const ull*)(sm + OB1);
#pragma unroll
        for (int j = 0; j < 32; j++) a2[j] = bb[j];
    }
#pragma unroll
    for (int c = 0; c < 64; c++) accum_row<32>(a2, sm + OW1 + c * 64, h1[c]);
    float h2[64];
#pragma unroll
    for (int j = 0; j < 32; j++) {
        float2 v = unpk(a2[j]);
        h2[2 * j + 0] = lrelu(v.x);
        h2[2 * j + 1] = lrelu(v.y);
    }

    // ---- layer 3: 64 -> 128, 4 chunks of 32, fused warp max-pool ----
    float* pool = sm + OPOOL + warp * 128;
#pragma unroll
    for (int ch = 0; ch < 4; ch++) {
        ull a3[16];
        {
            const ull* bb = (const ull*)(sm + OB2);
#pragma unroll
            for (int j = 0; j < 16; j++) a3[j] = bb[ch * 16 + j];
        }
#pragma unroll
        for (int c = 0; c < 64; c++)
            accum_row<16>(a3, sm + OW2 + c * 128 + ch * 32, h2[c]);
#pragma unroll
        for (int j = 0; j < 16; j++) {
            float2 v = unpk(a3[j]);
            float v0 = lrelu(v.x);
            float v1 = lrelu(v.y);
#pragma unroll
            for (int o = 16; o > 0; o >>= 1) {
                v0 = fmaxf(v0, __shfl_down_sync(0xffffffffu, v0, o));
                v1 = fmaxf(v1, __shfl_down_sync(0xffffffffu, v1, o));
            }
            if (lane == 0) {
                pool[ch * 32 + 2 * j + 0] = v0;
                pool[ch * 32 + 2 * j + 1] = v1;
            }
        }
    }
    __syncwarp();
    float4* dst = (float4*)(out + BB * NQ * 3 + (size_t)q * 128);
    dst[lane] = ((const float4*)pool)[lane];
}

// ---------------------------------------------------------------------------
extern "C" void kernel_launch(void* const* d_in, const int* in_sizes, int n_in,
                              void* d_out, int out_size)
{
    const float* xyz  = (const float*)d_in[0];
    const float* feat = (const float*)d_in[1];
    const float* W0   = (const float*)d_in[2];
    const float* b0   = (const float*)d_in[3];
    const float* W1   = (const float*)d_in[4];
    const float* b1   = (const float*)d_in[5];
    const float* W2   = (const float*)d_in[6];
    const float* b2   = (const float*)d_in[7];
    float* out = (float*)d_out;

    cudaFuncSetAttribute(mlp_kernel, cudaFuncAttributeMaxDynamicSharedMemorySize,
                         SMEM_MLP_BYTES);

    fps_kernel<<<BB, 1024>>>(xyz, out);
    knn_kernel<<<(BB * NQ) / 8, 256>>>(xyz, out);
    mlp_kernel<<<(BB * NQ) / 4, 128, SMEM_MLP_BYTES>>>(xyz, feat, W0, b0, W1, b1,
                                                       W2, b2, out);
}

// round 5
// speedup vs baseline: 6.8692x; 1.0039x over previous
#include <cuda_runtime.h>
#include <cuda_bf16.h>

typedef unsigned long long ull;

#define BB 8
#define NP 8192
#define NQ 1024
#define KNN 32
#define F1 64

// scratch: neighbor indices (radius-resolved), B*N2*K
__device__ int g_nbr[BB * NQ * KNN];

// ---------------- packed f32x2 helpers ----------------
union F2 { ull u; float2 f; };

__device__ __forceinline__ ull add2(ull a, ull b)
{
    ull r; asm("add.rn.f32x2 %0, %1, %2;" : "=l"(r) : "l"(a), "l"(b)); return r;
}
__device__ __forceinline__ ull mul2(ull a, ull b)
{
    ull r; asm("mul.rn.f32x2 %0, %1, %2;" : "=l"(r) : "l"(a), "l"(b)); return r;
}
__device__ __forceinline__ void fma2(ull& d, ull a, ull b)
{
    asm("fma.rn.f32x2 %0, %1, %2, %0;" : "+l"(d) : "l"(a), "l"(b));
}
__device__ __forceinline__ ull bc2(float x)
{
    ull r; asm("mov.b64 %0, {%1, %1};" : "=l"(r) : "f"(x)); return r;
}
__device__ __forceinline__ float2 unpk(ull r)
{
    float2 v; asm("mov.b64 {%0, %1}, %2;" : "=f"(v.x), "=f"(v.y) : "l"(r)); return v;
}
__device__ __forceinline__ float lrelu(float x) { return fmaxf(x, 0.2f * x); }

// ---------------------------------------------------------------------------
// Kernel 1: FPS. 1 block/batch, 1024 threads, 8 pts/thread in registers.
// 2 barriers/step. Exact argmax tie semantics (lowest global index).
// cur[] holds NEGATED coords so the distance loop needs no negation.
// ---------------------------------------------------------------------------
__global__ void __launch_bounds__(1024) fps_kernel(const float* __restrict__ xyz,
                                                   float* __restrict__ out)
{
    extern __shared__ float s[];            // sx/sy/sz: 3*8192 floats = 96KB
    float* sx = s;
    float* sy = s + NP;
    float* sz = s + 2 * NP;
    __shared__ float swv[32];
    __shared__ int   swi[32];
    __shared__ float cur[4];

    const int b = blockIdx.x;
    const int t = threadIdx.x;
    const int lane = t & 31;
    const int wid = t >> 5;
    const float* p = xyz + (size_t)b * NP * 3;

    ull px[4], py[4], pz[4];
    float md[8];
#pragma unroll
    for (int i = 0; i < 4; i++) {
        int i0 = t + (2 * i) * 1024;
        int i1 = t + (2 * i + 1) * 1024;
        F2 X, Y, Z;
        X.f.x = p[i0 * 3 + 0]; Y.f.x = p[i0 * 3 + 1]; Z.f.x = p[i0 * 3 + 2];
        X.f.y = p[i1 * 3 + 0]; Y.f.y = p[i1 * 3 + 1]; Z.f.y = p[i1 * 3 + 2];
        px[i] = X.u; py[i] = Y.u; pz[i] = Z.u;
        sx[i0] = X.f.x; sy[i0] = Y.f.x; sz[i0] = Z.f.x;
        sx[i1] = X.f.y; sy[i1] = Y.f.y; sz[i1] = Z.f.y;
        md[2 * i] = 3.402823466e38f;
        md[2 * i + 1] = 3.402823466e38f;
    }
    if (t == 0) {
        cur[0] = -p[0]; cur[1] = -p[1]; cur[2] = -p[2];
        float* o = out + (size_t)b * NQ * 3;
        o[0] = p[0]; o[1] = p[1]; o[2] = p[2];
    }
    __syncthreads();

    for (int si = 1; si < NQ; si++) {
        const ull ncx = bc2(cur[0]), ncy = bc2(cur[1]), ncz = bc2(cur[2]);
        float tv = -1.0f;
#pragma unroll
        for (int i = 0; i < 4; i++) {
            ull dx = add2(px[i], ncx);
            ull dy = add2(py[i], ncy);
            ull dz = add2(pz[i], ncz);
            ull d = mul2(dx, dx);
            fma2(d, dy, dy);
            fma2(d, dz, dz);
            float2 D = unpk(d);
            md[2 * i]     = fminf(md[2 * i], D.x);
            md[2 * i + 1] = fminf(md[2 * i + 1], D.y);
            tv = fmaxf(tv, md[2 * i]);
            tv = fmaxf(tv, md[2 * i + 1]);
        }
        // warp max (value only)
        float wv = tv;
#pragma unroll
        for (int o = 16; o > 0; o >>= 1)
            wv = fmaxf(wv, __shfl_xor_sync(0xffffffffu, wv, o));
        // lowest global index for this lane if it matches the warp max
        int idx = 0x7fffffff;
        if (tv == wv) {
#pragma unroll
            for (int i = 7; i >= 0; i--)
                if (md[i] == wv) idx = t + (i << 10);
        }
        const unsigned mask = __ballot_sync(0xffffffffu, tv == wv);
        bool iwin;
        if (__popc(mask) > 1) {             // rare: value tie across lanes
            int mi = idx;
#pragma unroll
            for (int o = 16; o > 0; o >>= 1)
                mi = min(mi, __shfl_xor_sync(0xffffffffu, mi, o));
            iwin = (idx == mi);             // idx unique per lane -> unique winner
        } else {
            iwin = (tv == wv);
        }
        if (iwin) { swv[wid] = wv; swi[wid] = idx; }
        __syncthreads();                                   // (1)
        if (t < 32) {
            float v = swv[t];
            int id = swi[t];
#pragma unroll
            for (int o = 16; o > 0; o >>= 1) {
                float ov = __shfl_xor_sync(0xffffffffu, v, o);
                int  oid = __shfl_xor_sync(0xffffffffu, id, o);
                if (ov > v || (ov == v && oid < id)) { v = ov; id = oid; }
            }
            if (t == 0) {
                float wx = sx[id], wy = sy[id], wz = sz[id];
                cur[0] = -wx; cur[1] = -wy; cur[2] = -wz;
                float* o2 = out + (size_t)b * NQ * 3 + si * 3;
                o2[0] = wx; o2[1] = wy; o2[2] = wz;
            }
        }
        __syncthreads();                                   // (2)
    }
}

// ---------------------------------------------------------------------------
// Kernel 2: warp-per-query 32-NN, radius pre-prune, append-then-sort.
// Exact lax.top_k stable-tie semantics via (encoded d2, idx) u64 keys.
// ---------------------------------------------------------------------------
__device__ __forceinline__ void isort(ull* a, int n)
{
    for (int i = 1; i < n; i++) {
        ull k = a[i];
        int m = i;
        while (m > 0 && a[m - 1] > k) { a[m] = a[m - 1]; m--; }
        a[m] = k;
    }
}

__global__ void __launch_bounds__(256) knn_kernel(const float* __restrict__ xyz,
                                                  const float* __restrict__ outxyz)
{
    __shared__ float4 sp[1024];                 // 16KB tile

    const int warp = threadIdx.x >> 5;
    const int lane = threadIdx.x & 31;
    const int gq = blockIdx.x * 8 + warp;       // global query id
    const int b = blockIdx.x >> 7;              // 128 blocks per batch

    const float qx = outxyz[gq * 3 + 0];
    const float qy = outxyz[gq * 3 + 1];
    const float qz = outxyz[gq * 3 + 2];
    const float q2 = fmaf(qx, qx, fmaf(qy, qy, qz * qz));

    ull arr[KNN];
    int cnt = 0;
    ull klim = ~0ull;
    bool sorted = false;
    const float r2 = 0.04f;

    const float* p = xyz + (size_t)b * NP * 3;

    for (int tile = 0; tile < 8; tile++) {
        const int base = tile << 10;
        for (int j = threadIdx.x; j < 1024; j += 256) {
            float x = p[(base + j) * 3 + 0];
            float y = p[(base + j) * 3 + 1];
            float z = p[(base + j) * 3 + 2];
            sp[j] = make_float4(x, y, z, fmaf(x, x, fmaf(y, y, z * z)));
        }
        __syncthreads();
#pragma unroll 4
        for (int jj = 0; jj < 32; jj++) {
            const int j = (jj << 5) + lane;
            float4 P = sp[j];
            float qp = fmaf(qx, P.x, fmaf(qy, P.y, qz * P.z));
            float d2 = fmaf(-2.0f, qp, q2 + P.w);
            if (d2 <= r2) {                                  // radius pre-prune
                unsigned du = __float_as_uint(d2);
                du ^= (unsigned)((int)du >> 31) | 0x80000000u;
                ull key = ((ull)du << 32) | (unsigned)(base + j);
                if (!sorted) {
                    arr[cnt++] = key;                        // cheap append
                    if (cnt == KNN) { isort(arr, KNN); klim = arr[KNN - 1]; sorted = true; }
                } else if (key < klim) {                     // rare overflow path
                    int m = KNN - 1;
                    while (m > 0 && arr[m - 1] > key) { arr[m] = arr[m - 1]; m--; }
                    arr[m] = key;
                    klim = arr[KNN - 1];
                }
            }
        }
        __syncthreads();
    }
    if (!sorted) isort(arr, cnt);

    // exact warp merge: 32 rounds of extract-min over per-lane sorted lists
    ull h = (cnt > 0) ? arr[0] : ~0ull;
    int ptr = 1;
    int nearidx = 0;
    int* dst = g_nbr + (size_t)gq * KNN;
    for (int k = 0; k < KNN; k++) {
        ull m = h;
#pragma unroll
        for (int o = 16; o > 0; o >>= 1) {
            ull x = __shfl_xor_sync(0xffffffffu, m, o);
            if (x < m) m = x;
        }
        if (k == 0) nearidx = (int)(m & 0xffffffffu);    // self always within radius
        int wi = (m == ~0ull) ? nearidx : (int)(m & 0xffffffffu);
        if (lane == k) dst[k] = wi;
        if (h == m && m != ~0ull)
            h = (ptr < cnt) ? arr[ptr++] : ~0ull;
    }
}

// ---------------------------------------------------------------------------
// Kernel 3: gather + MLP(67->64->64->128, leaky 0.2) + max over K (unchanged).
// ---------------------------------------------------------------------------
template <int NU>
__device__ __forceinline__ void accum_row(ull* acc, const float* wrow, float xc)
{
    ull xv = bc2(xc);
    const ulonglong2* w = (const ulonglong2*)wrow;
#pragma unroll
    for (int jj = 0; jj < NU / 2; jj++) {
        ulonglong2 ww = w[jj];
        fma2(acc[2 * jj + 0], xv, ww.x);
        fma2(acc[2 * jj + 1], xv, ww.y);
    }
}

#define OW0 0
#define OB0 4288
#define OW1 4352
#define OB1 8448
#define OW2 8512
#define OB2 16704
#define OPOOL 16832
#define SMEM_MLP_FLOATS (OPOOL + 4 * 128)
#define SMEM_MLP_BYTES (SMEM_MLP_FLOATS * 4)

__global__ void __launch_bounds__(128, 3) mlp_kernel(
    const float* __restrict__ xyz, const float* __restrict__ feat,
    const float* __restrict__ W0, const float* __restrict__ b0,
    const float* __restrict__ W1, const float* __restrict__ b1,
    const float* __restrict__ W2, const float* __restrict__ b2,
    float* __restrict__ out)
{
    extern __shared__ float sm[];
    for (int i = threadIdx.x; i < OPOOL; i += 128) {
        float v;
        if (i < OB0)        v = W0[i];
        else if (i < OW1)   v = b0[i - OB0];
        else if (i < OB1)   v = W1[i - OW1];
        else if (i < OW2)   v = b1[i - OB1];
        else if (i < OB2)   v = W2[i - OW2];
        else                v = b2[i - OB2];
        sm[i] = v;
    }
    __syncthreads();

    const int warp = threadIdx.x >> 5;
    const int lane = threadIdx.x & 31;
    const int q = blockIdx.x * 4 + warp;
    const int b = q >> 10;

    const int nidx = g_nbr[q * KNN + lane];
    const float cx = out[q * 3 + 0];
    const float cy = out[q * 3 + 1];
    const float cz = out[q * 3 + 2];
    const float* pp = xyz + ((size_t)b * NP + nidx) * 3;
    const float x0 = pp[0] - cx;
    const float x1 = pp[1] - cy;
    const float x2 = pp[2] - cz;
    const float4* pf = (const float4*)(feat + ((size_t)b * NP + nidx) * F1);

    // ---- layer 1: 67 -> 64 ----
    ull a1[32];
    {
        const ull* bb = (const ull*)(sm + OB0);
#pragma unroll
        for (int j = 0; j < 32; j++) a1[j] = bb[j];
    }
    accum_row<32>(a1, sm + OW0 + 0 * 64, x0);
    accum_row<32>(a1, sm + OW0 + 1 * 64, x1);
    accum_row<32>(a1, sm + OW0 + 2 * 64, x2);
#pragma unroll
    for (int g = 0; g < 16; g++) {
        float4 f = pf[g];
        accum_row<32>(a1, sm + OW0 + (3 + 4 * g + 0) * 64, f.x);
        accum_row<32>(a1, sm + OW0 + (3 + 4 * g + 1) * 64, f.y);
        accum_row<32>(a1, sm + OW0 + (3 + 4 * g + 2) * 64, f.z);
        accum_row<32>(a1, sm + OW0 + (3 + 4 * g + 3) * 64, f.w);
    }
    float h1[64];
#pragma unroll
    for (int j = 0; j < 32; j++) {
        float2 v = unpk(a1[j]);
        h1[2 * j + 0] = lrelu(v.x);
        h1[2 * j + 1] = lrelu(v.y);
    }

    // ---- layer 2: 64 -> 64 ----
    ull a2[32];
    {
        const ull* bb = (const ull*)(sm + OB1);
#pragma unroll
        for (int j = 0; j < 32; j++) a2[j] = bb[j];
    }
#pragma unroll
    for (int c = 0; c < 64; c++) accum_row<32>(a2, sm + OW1 + c * 64, h1[c]);
    float h2[64];
#pragma unroll
    for (int j = 0; j < 32; j++) {
        float2 v = unpk(a2[j]);
        h2[2 * j + 0] = lrelu(v.x);
        h2[2 * j + 1] = lrelu(v.y);
    }

    // ---- layer 3: 64 -> 128, 4 chunks of 32, fused warp max-pool ----
    float* pool = sm + OPOOL + warp * 128;
#pragma unroll
    for (int ch = 0; ch < 4; ch++) {
        ull a3[16];
        {
            const ull* bb = (const ull*)(sm + OB2);
#pragma unroll
            for (int j = 0; j < 16; j++) a3[j] = bb[ch * 16 + j];
        }
#pragma unroll
        for (int c = 0; c < 64; c++)
            accum_row<16>(a3, sm + OW2 + c * 128 + ch * 32, h2[c]);
#pragma unroll
        for (int j = 0; j < 16; j++) {
            float2 v = unpk(a3[j]);
            float v0 = lrelu(v.x);
            float v1 = lrelu(v.y);
#pragma unroll
            for (int o = 16; o > 0; o >>= 1) {
                v0 = fmaxf(v0, __shfl_down_sync(0xffffffffu, v0, o));
                v1 = fmaxf(v1, __shfl_down_sync(0xffffffffu, v1, o));
            }
            if (lane == 0) {
                pool[ch * 32 + 2 * j + 0] = v0;
                pool[ch * 32 + 2 * j + 1] = v1;
            }
        }
    }
    __syncwarp();
    float4* dst = (float4*)(out + BB * NQ * 3 + (size_t)q * 128);
    dst[lane] = ((const float4*)pool)[lane];
}

// ---------------------------------------------------------------------------
extern "C" void kernel_launch(void* const* d_in, const int* in_sizes, int n_in,
                              void* d_out, int out_size)
{
    const float* xyz  = (const float*)d_in[0];
    const float* feat = (const float*)d_in[1];
    const float* W0   = (const float*)d_in[2];
    const float* b0   = (const float*)d_in[3];
    const float* W1   = (const float*)d_in[4];
    const float* b1   = (const float*)d_in[5];
    const float* W2   = (const float*)d_in[6];
    const float* b2   = (const float*)d_in[7];
    float* out = (float*)d_out;

    cudaFuncSetAttribute(fps_kernel, cudaFuncAttributeMaxDynamicSharedMemorySize,
                         3 * NP * 4);
    cudaFuncSetAttribute(mlp_kernel, cudaFuncAttributeMaxDynamicSharedMemorySize,
                         SMEM_MLP_BYTES);

    fps_kernel<<<BB, 1024, 3 * NP * 4>>>(xyz, out);
    knn_kernel<<<(BB * NQ) / 8, 256>>>(xyz, out);
    mlp_kernel<<<(BB * NQ) / 4, 128, SMEM_MLP_BYTES>>>(xyz, feat, W0, b0, W1, b1,
                                                       W2, b2, out);
}